// round 11
// baseline (speedup 1.0000x reference)
#include <cuda_runtime.h>

#define Hh 51
#define H4 204
#define TT 1024
#define NCTA 128
#define NTHR 832   // warps 0-12: L1 (A) + head in warp-12 hi lanes; warps 13-25: L2 (B)

// ---- shared memory (float offsets) ----
// Weights: [204][56] rows (cols 51..55 zero). stride 56 floats = 14 chunks ->
//   4j x 2ch chunk residues {0,6,4,2}+{7,5,3,1}: conflict-free.
// W2h at +4 floats (16B) past 2*11424 -> +1 chunk vs W2i: B's dual-matrix loads conflict-free.
// h arrays: [2 buf][480] gapped k-pair layout: pair p at POFF(p)=p*16+(p>=14?16:0);
//   buf stride 480 (1920B % 128 == 0, bank-neutral); OFF_H2-OFF_H1=976 (3904B % 128 == 64).
#define OFF_W1   0
#define OFF_W2I  11424
#define OFF_W2H  22852
#define OFF_WLIN 34276
#define OFF_X    34328
#define OFF_H1   42528
#define OFF_H2   43504
#define SMEM_FLOATS 44464
#define SMEM_BYTES  (SMEM_FLOATS * 4)

#define POFF(p) ((p) * 16 + ((p) >= 14 ? 16 : 0))

typedef unsigned long long u64;

__device__ __forceinline__ u64 splat2(float w) {
    unsigned int wi = __float_as_uint(w);
    u64 r;
    asm("mov.b64 %0, {%1, %1};" : "=l"(r) : "r"(wi));
    return r;
}
__device__ __forceinline__ void ffma2(u64& d, u64 a, u64 b) {
    asm("fma.rn.f32x2 %0, %1, %2, %0;" : "+l"(d) : "l"(a), "l"(b));
}
__device__ __forceinline__ float2 u2f(u64 v) {
    float2 f;
    asm("mov.b64 {%0, %1}, %2;" : "=f"(f.x), "=f"(f.y) : "l"(v));
    return f;
}
__device__ __forceinline__ u64 f2u(float x, float y) {
    u64 v;
    asm("mov.b64 %0, {%1, %2};" : "=l"(v) : "f"(x), "f"(y));
    return v;
}
__device__ __forceinline__ float sigf(float x) {
    return __fdividef(1.0f, 1.0f + __expf(-x));
}
__device__ __forceinline__ float tanhfast(float x) {
    return 1.0f - __fdividef(2.0f, __expf(2.0f * x) + 1.0f);
}
__device__ __forceinline__ void bar_arrive(int id) {
    asm volatile("bar.arrive %0, %1;" :: "r"(id), "r"(NTHR) : "memory");
}
__device__ __forceinline__ void bar_wait(int id) {
    asm volatile("bar.sync %0, %1;" :: "r"(id), "r"(NTHR) : "memory");
}

// one quad: 4 weight float4 (one per gate row) x 2 h-pair LDS -> 16 FFMA2
#define QUAD(wc, hoff) { \
    const float4 wi = *(const float4*)(wp0 + (wc)); \
    const float4 wf = *(const float4*)(wp1 + (wc)); \
    const float4 wg = *(const float4*)(wp2 + (wc)); \
    const float4 wo = *(const float4*)(wp3 + (wc)); \
    const ulonglong2 v0 = *(const ulonglong2*)(hbase + (hoff)); \
    const ulonglong2 v1 = *(const ulonglong2*)(hbase + (hoff) + 16); \
    ffma2(ai, splat2(wi.x), v0.x); ffma2(ai, splat2(wi.y), v0.y); \
    ffma2(ai, splat2(wi.z), v1.x); ffma2(ai, splat2(wi.w), v1.y); \
    ffma2(af, splat2(wf.x), v0.x); ffma2(af, splat2(wf.y), v0.y); \
    ffma2(af, splat2(wf.z), v1.x); ffma2(af, splat2(wf.w), v1.y); \
    ffma2(ag, splat2(wg.x), v0.x); ffma2(ag, splat2(wg.y), v0.y); \
    ffma2(ag, splat2(wg.z), v1.x); ffma2(ag, splat2(wg.w), v1.y); \
    ffma2(ao, splat2(wo.x), v0.x); ffma2(ao, splat2(wo.y), v0.y); \
    ffma2(ao, splat2(wo.z), v1.x); ffma2(ao, splat2(wo.w), v1.y); }

#define REDUCE4(msk) { \
    u64 x_; \
    x_ = __shfl_xor_sync((msk), ai, 4); \
    asm("add.rn.f32x2 %0, %0, %1;" : "+l"(ai) : "l"(x_)); \
    x_ = __shfl_xor_sync((msk), af, 4); \
    asm("add.rn.f32x2 %0, %0, %1;" : "+l"(af) : "l"(x_)); \
    x_ = __shfl_xor_sync((msk), ag, 4); \
    asm("add.rn.f32x2 %0, %0, %1;" : "+l"(ag) : "l"(x_)); \
    x_ = __shfl_xor_sync((msk), ao, 4); \
    asm("add.rn.f32x2 %0, %0, %1;" : "+l"(ao) : "l"(x_)); }

#define UPDATE(cvar, hout) { \
    const float2 gi = u2f(ai), gf = u2f(af), gg = u2f(ag), go = u2f(ao); \
    const float i0 = sigf(gi.x), f0 = sigf(gf.x), g0 = tanhfast(gg.x), o0 = sigf(go.x); \
    const float i1 = sigf(gi.y), f1 = sigf(gf.y), g1 = tanhfast(gg.y), o1 = sigf(go.y); \
    cvar.x = f0 * cvar.x + i0 * g0; \
    cvar.y = f1 * cvar.y + i1 * g1; \
    hout = f2u(o0 * tanhfast(cvar.x), o1 * tanhfast(cvar.y)); }

__global__ __launch_bounds__(NTHR, 1)
void lstm_seq_kernel(const float* __restrict__ input,
                     const float* __restrict__ W_ih1, const float* __restrict__ W_hh1,
                     const float* __restrict__ b_ih1, const float* __restrict__ b_hh1,
                     const float* __restrict__ W_ih2, const float* __restrict__ W_hh2,
                     const float* __restrict__ b_ih2, const float* __restrict__ b_hh2,
                     const float* __restrict__ W_lin, const float* __restrict__ b_lin,
                     float* __restrict__ out)
{
    extern __shared__ float sm[];
    float* sW1   = sm + OFF_W1;
    float* sW2i  = sm + OFF_W2I;
    float* sW2h  = sm + OFF_W2H;
    float* sWlin = sm + OFF_WLIN;
    float* sX    = sm + OFF_X;
    float* sH1   = sm + OFF_H1;   // [2][480]
    float* sH2   = sm + OFF_H2;   // [2][480]

    const int tid = threadIdx.x;
    const int b0  = blockIdx.x * 8;

    // ---------------- staging ----------------
    for (int i = tid; i < OFF_WLIN; i += NTHR) sm[i] = 0.0f;    // zero all weight rows (incl pads)
    for (int i = tid; i < 1936; i += NTHR) sH1[i] = 0.0f;       // zero h1+h2 (both bufs + gaps)
    __syncthreads();
    for (int i = tid; i < H4 * Hh; i += NTHR) {
        const int r = i / Hh, k = i % Hh;
        sW1[r * 56 + k]  = W_hh1[i];
        sW2i[r * 56 + k] = W_ih2[i];
        sW2h[r * 56 + k] = W_hh2[i];
    }
    if (tid < 52) sWlin[tid] = (tid < Hh) ? W_lin[tid] : 0.0f;
    for (int i = tid; i < 8 * TT; i += NTHR) {
        const int b = i >> 10, t = i & 1023;
        sX[t * 8 + b] = input[b0 * TT + i];
    }

    // ---------------- roles ----------------
    const bool isA = (tid < 416);
    const int  gt  = isA ? tid : (tid - 416);  // 0..415
    const int  bp  = gt & 3;
    const int  ch  = (gt >> 2) & 1;
    const int  jr  = gt >> 3;                  // 0..51
    const int  j   = (jr < Hh) ? jr : (Hh - 1);
    const bool valid = (jr < Hh);
    // head: A warp 12 lanes 24..31 (jr == 51)
    const bool ishead = isA && !valid;
    const int  hbb = gt - 408;                 // 0..7 for head lanes
    // shuffle masks: A warp 12 gate lanes exclude head lanes
    const unsigned amask = (isA && (tid >> 5) == 12) ? 0x00FFFFFFu : 0xFFFFFFFFu;

    const int ri = j, rf = Hh + j, rg = 2 * Hh + j, ro = 3 * Hh + j;
    u64 sd_i = 0, sd_f = 0, sd_g = 0, sd_o = 0;   // acc seeds (ch0 carries bias)
    u64 wxi = 0, wxf = 0, wxg = 0, wxo = 0;
    const float *wp0, *wp1, *wp2, *wp3;
    if (isA) {
        const int cb = ch * 28;                   // k-half column base
        wp0 = sW1 + ri * 56 + cb; wp1 = sW1 + rf * 56 + cb;
        wp2 = sW1 + rg * 56 + cb; wp3 = sW1 + ro * 56 + cb;
        if (ch == 0) {
            sd_i = splat2(b_ih1[ri] + b_hh1[ri]);
            sd_f = splat2(b_ih1[rf] + b_hh1[rf]);
            sd_g = splat2(b_ih1[rg] + b_hh1[rg]);
            sd_o = splat2(b_ih1[ro] + b_hh1[ro]);
            wxi = splat2(W_ih1[ri]); wxf = splat2(W_ih1[rf]);
            wxg = splat2(W_ih1[rg]); wxo = splat2(W_ih1[ro]);
        }
    } else {
        const float* wb = ch ? sW2h : sW2i;       // ch0 = ih2 (over h1), ch1 = hh2 (over h2)
        wp0 = wb + ri * 56; wp1 = wb + rf * 56;
        wp2 = wb + rg * 56; wp3 = wb + ro * 56;
        if (ch == 0) {
            sd_i = splat2(b_ih2[ri] + b_hh2[ri]);
            sd_f = splat2(b_ih2[rf] + b_hh2[rf]);
            sd_g = splat2(b_ih2[rg] + b_hh2[rg]);
            sd_o = splat2(b_ih2[ro] + b_hh2[ro]);
        }
    }
    // store offset (ch0 stores)
    const int pj  = j >> 1;
    const int sto = POFF(pj) + bp * 4 + (j & 1) * 2;
    // A h-read base offset within buf: ch half + bp
    const int hA = ch * 240 + bp * 4;

    float2 cc = make_float2(0.0f, 0.0f);
    const float blin = b_lin[0];

    __syncthreads();

    // ---------------- prologue: A computes h1(0) into buf 0 ----------------
    if (isA) {
        if (!ishead) {
            u64 ai = sd_i, af = sd_f, ag = sd_g, ao = sd_o;
            if (ch == 0) {
                const u64 xv = *(const u64*)(sX + bp * 2);
                ffma2(ai, wxi, xv); ffma2(af, wxf, xv);
                ffma2(ag, wxg, xv); ffma2(ao, wxo, xv);
            }
            const float* hbase = sH1 + 480 + hA;   // buf 1: zeros
            #pragma unroll
            for (int s = 0; s < 7; ++s) QUAD(s * 4, s * 32)
            REDUCE4(amask)
            u64 hnew;
            UPDATE(cc, hnew);
            if (valid && ch == 0) *(u64*)(sH1 + sto) = hnew;
        }
        bar_arrive(1);                              // h1(0) ready
    } else {
        bar_arrive(2);
    }

    // ---------------- time loop ----------------
    for (int t = 0; t < TT; ++t) {
        const int pt = t & 1, pn = pt ^ 1;

        if (isA) {
            bar_wait(2);                            // B(t-1) done
            if (!ishead) {
                if (t < TT - 1) {
                    // h1(t+1): x(t+1) + W_hh1 . h1(t)[pt] -> buf pn
                    u64 ai = sd_i, af = sd_f, ag = sd_g, ao = sd_o;
                    if (ch == 0) {
                        const u64 xv = *(const u64*)(sX + (t + 1) * 8 + bp * 2);
                        ffma2(ai, wxi, xv); ffma2(af, wxf, xv);
                        ffma2(ag, wxg, xv); ffma2(ao, wxo, xv);
                    }
                    const float* hbase = sH1 + pt * 480 + hA;
                    #pragma unroll
                    for (int s = 0; s < 7; ++s) QUAD(s * 4, s * 32)
                    REDUCE4(amask)
                    u64 hnew;
                    UPDATE(cc, hnew);
                    if (valid && ch == 0) *(u64*)(sH1 + pn * 480 + sto) = hnew;
                }
            } else if (t >= 1) {
                // head(t-1): reads h2(t-1)[pn]
                const float* h2r = sH2 + pn * 480;
                float p = 0.0f;
                #pragma unroll
                for (int k = 0; k < Hh; ++k)
                    p = fmaf(sWlin[k],
                             h2r[POFF(k >> 1) + (hbb >> 1) * 4 + (k & 1) * 2 + (hbb & 1)],
                             p);
                out[(b0 + hbb) * TT + (t - 1)] = p + blin;
            }
            if (t < TT - 1) bar_arrive(1);          // h1(t+1) ready
        } else {
            bar_wait(1);                            // h1(t) ready
            // L2 cell(t): ch0 = W_ih2 . h1(t)[pt]; ch1 = W_hh2 . h2(t-1)[pn]
            u64 ai = sd_i, af = sd_f, ag = sd_g, ao = sd_o;
            const float* hbase = (ch ? (sH2 + pn * 480) : (sH1 + pt * 480)) + bp * 4;
            #pragma unroll
            for (int s = 0; s < 13; ++s) QUAD(s * 4, s * 32 + ((s >= 7) ? 16 : 0))
            REDUCE4(0xFFFFFFFFu)
            u64 hnew;
            UPDATE(cc, hnew);
            if (valid && ch == 0) *(u64*)(sH2 + pt * 480 + sto) = hnew;
            bar_arrive(2);
        }
    }

    // ---------------- epilogue: head(TT-1) ----------------
    if (isA) {
        bar_wait(2);
        if (ishead) {
            const float* h2r = sH2 + ((TT - 1) & 1) * 480;
            float p = 0.0f;
            #pragma unroll
            for (int k = 0; k < Hh; ++k)
                p = fmaf(sWlin[k],
                         h2r[POFF(k >> 1) + (hbb >> 1) * 4 + (k & 1) * 2 + (hbb & 1)],
                         p);
            out[(b0 + hbb) * TT + (TT - 1)] = p + blin;
        }
    }
}

extern "C" void kernel_launch(void* const* d_in, const int* in_sizes, int n_in,
                              void* d_out, int out_size) {
    const float* input = (const float*)d_in[0];
    const float* W_ih1 = (const float*)d_in[1];
    const float* W_hh1 = (const float*)d_in[2];
    const float* b_ih1 = (const float*)d_in[3];
    const float* b_hh1 = (const float*)d_in[4];
    const float* W_ih2 = (const float*)d_in[5];
    const float* W_hh2 = (const float*)d_in[6];
    const float* b_ih2 = (const float*)d_in[7];
    const float* b_hh2 = (const float*)d_in[8];
    const float* W_lin = (const float*)d_in[9];
    const float* b_lin = (const float*)d_in[10];
    float* out = (float*)d_out;

    cudaFuncSetAttribute(lstm_seq_kernel,
                         cudaFuncAttributeMaxDynamicSharedMemorySize, SMEM_BYTES);
    lstm_seq_kernel<<<NCTA, NTHR, SMEM_BYTES>>>(
        input, W_ih1, W_hh1, b_ih1, b_hh1,
        W_ih2, W_hh2, b_ih2, b_hh2, W_lin, b_lin, out);
}